// round 3
// baseline (speedup 1.0000x reference)
#include <cuda_runtime.h>

#define NN 320
#define DD 64

// Precomputed, perm-independent state (static device globals: no allocation).
__device__ float d_Dp[NN*NN];   // ||x_a - x_b||
__device__ float d_Dl[NN*NN];   // Delta = ||x_a + x_b|| - ||x_a - x_b||
__device__ float d_G [NN*NN];   // Gram: x_a . x_b
__device__ float d_RD[NN];      // row sums of Delta (incl. diagonal)
__device__ float d_rowC[NN];    // per-row sum of Dp over b>a
__device__ float d_sn[NN];      // squared norms
__device__ float d_X1[DD];      // column sum of data
__device__ float d_qd[NN];      // X1 . x_a
__device__ float d_scal[3];     // [0]=C_Dp  [1]=S1=sum sn  [2]=||X1||^2

__device__ __forceinline__ float warpRed(float v){
#pragma unroll
    for (int o = 16; o > 0; o >>= 1) v += __shfl_down_sync(0xffffffffu, v, o);
    return v;
}

// Kernel 1: squared norms + column sum X1
__global__ void k_pre1(const float* __restrict__ x){
    int t = threadIdx.x;
    const float4* r = reinterpret_cast<const float4*>(x + t*DD);
    float s = 0.f;
#pragma unroll
    for (int i = 0; i < DD/4; i++){ float4 v = r[i]; s += v.x*v.x + v.y*v.y + v.z*v.z + v.w*v.w; }
    d_sn[t] = s;
    if (t < DD){
        float acc = 0.f;
#pragma unroll 4
        for (int a = 0; a < NN; a++) acc += x[a*DD + t];
        d_X1[t] = acc;
    }
}

// Kernel 2: Dp, Delta, Gram, row sums. One block per row a, thread = column b.
__global__ void __launch_bounds__(NN) k_pre2(const float* __restrict__ x){
    __shared__ float xa[DD];
    __shared__ float red[2][10];
    int a = blockIdx.x, b = threadIdx.x;
    if (b < DD) xa[b] = x[a*DD + b];
    __syncthreads();
    const float4* xb = reinterpret_cast<const float4*>(x + b*DD);
    float g = 0.f;
#pragma unroll
    for (int i = 0; i < DD/4; i++){
        float4 v = xb[i];
        g += xa[4*i]*v.x + xa[4*i+1]*v.y + xa[4*i+2]*v.z + xa[4*i+3]*v.w;
    }
    float sa = d_sn[a], sb = d_sn[b];
    float dp = sqrtf(fmaxf(sa + sb - 2.f*g, 0.f));
    float dm = sqrtf(fmaxf(sa + sb + 2.f*g, 0.f));
    float dl = dm - dp;
    d_Dp[a*NN + b] = dp;
    d_Dl[a*NN + b] = dl;
    d_G [a*NN + b] = g;
    int w = b >> 5, l = b & 31;
    float v0 = warpRed(dl);
    float v1 = warpRed(b > a ? dp : 0.f);
    if (l == 0){ red[0][w] = v0; red[1][w] = v1; }
    __syncthreads();
    if (b == 0){
        float s0 = 0.f, s1 = 0.f;
#pragma unroll
        for (int i = 0; i < 10; i++){ s0 += red[0][i]; s1 += red[1][i]; }
        d_RD[a]   = s0;
        d_rowC[a] = s1;
    }
}

// Kernel 3: qd[a] = X1 . x_a, plus scalar reductions
__global__ void __launch_bounds__(NN) k_pre3(const float* __restrict__ x){
    __shared__ float X1s[DD];
    __shared__ float red[3][10];
    int t = threadIdx.x, w = t >> 5, l = t & 31;
    if (t < DD) X1s[t] = d_X1[t];
    __syncthreads();
    float q = 0.f;
#pragma unroll
    for (int d = 0; d < DD; d++) q += X1s[d] * x[t*DD + d];
    d_qd[t] = q;
    float v0 = warpRed(d_rowC[t]);
    float v1 = warpRed(d_sn[t]);
    float v2 = warpRed(t < DD ? X1s[t]*X1s[t] : 0.f);
    if (l == 0){ red[0][w] = v0; red[1][w] = v1; red[2][w] = v2; }
    __syncthreads();
    if (t == 0){
        float s0 = 0.f, s1 = 0.f, s2 = 0.f;
#pragma unroll
        for (int i = 0; i < 10; i++){ s0 += red[0][i]; s1 += red[1][i]; s2 += red[2][i]; }
        d_scal[0] = s0; d_scal[1] = s1; d_scal[2] = s2;
    }
}

// Kernel 4: one block per dataset (block 0 = identity, block p>=1 = perms[p-1]).
// 320 threads = 80 quad-columns x 4 row-slices. float4 gathers.
__global__ void __launch_bounds__(NN, 4) k_main(const int* __restrict__ ptype,
                                                const int* __restrict__ perms,
                                                float* __restrict__ out){
    __shared__ float beta[NN], chi[NN];
    __shared__ int   Bl[NN], Cl[NN];
    __shared__ int   offB[10], offC[10], cnt[2];
    __shared__ float4 s4[3][4][NN/4];     // [Dl | G | Dp][slice][quad-col]
    __shared__ float red[6][10];

    int t = threadIdx.x, p = blockIdx.x;
    int w = t >> 5, l = t & 31;

    beta[t] = 0.f; chi[t] = 0.f;
    __syncthreads();

    int a  = (p == 0) ? t : perms[(p-1)*NN + t];
    int fn = (ptype[t] == 0);
    int fa = (ptype[a] == 0);
    int u  = (a != t) && fn && fa;          // this position's row is negated
    if (fn) chi[a]  = 1.f;                  // image of a fermion position
    if (u)  beta[a] = 1.f;                  // image of a negated position

    // Deterministic warp-ballot compaction into index lists
    unsigned ballB = __ballot_sync(0xffffffffu, u);
    unsigned ballC = __ballot_sync(0xffffffffu, fn);
    if (l == 0){ offB[w] = __popc(ballB); offC[w] = __popc(ballC); }
    __syncthreads();
    if (t == 0){
        int sB = 0, sC = 0;
#pragma unroll
        for (int i = 0; i < 10; i++){
            int bb = offB[i]; offB[i] = sB; sB += bb;
            int cc = offC[i]; offC[i] = sC; sC += cc;
        }
        cnt[0] = sB; cnt[1] = sC;
    }
    __syncthreads();
    unsigned lt = (1u << l) - 1u;
    if (u)  Bl[offB[w] + __popc(ballB & lt)] = a;
    if (fn) Cl[offC[w] + __popc(ballC & lt)] = a;
    __syncthreads();
    int Bc = cnt[0], Cc = cnt[1];

    // Column-sum gathers, float4 per thread. slice s handles rows s, s+4, ...
    int s = t / 80;           // 0..3
    int q = t - s*80;         // 0..79 quad-column
    const float* pDl = d_Dl + 4*q;
    const float* pG  = d_G  + 4*q;
    const float* pDp = d_Dp + 4*q;

    float4 aB = make_float4(0.f,0.f,0.f,0.f);
    float4 aG = make_float4(0.f,0.f,0.f,0.f);
    float4 aX = make_float4(0.f,0.f,0.f,0.f);
#pragma unroll 2
    for (int i = s; i < Bc; i += 4){
        int r = Bl[i] * NN;
        float4 v = *reinterpret_cast<const float4*>(pDl + r);
        float4 g = *reinterpret_cast<const float4*>(pG  + r);
        aB.x += v.x; aB.y += v.y; aB.z += v.z; aB.w += v.w;
        aG.x += g.x; aG.y += g.y; aG.z += g.z; aG.w += g.w;
    }
#pragma unroll 4
    for (int i = s; i < Cc; i += 4){
        int r = Cl[i] * NN;
        float4 v = *reinterpret_cast<const float4*>(pDp + r);
        aX.x += v.x; aX.y += v.y; aX.z += v.z; aX.w += v.w;
    }
    s4[0][s][q] = aB;
    s4[1][s][q] = aG;
    s4[2][s][q] = aX;
    __syncthreads();

    // Per-column totals (thread t = column t), then weighted reductions.
    const float* f0 = reinterpret_cast<const float*>(s4[0]);
    const float* f1 = reinterpret_cast<const float*>(s4[1]);
    const float* f2 = reinterpret_cast<const float*>(s4[2]);
    float colB = f0[t] + f0[NN+t] + f0[2*NN+t] + f0[3*NN+t];
    float colG = f1[t] + f1[NN+t] + f1[2*NN+t] + f1[3*NN+t];
    float colX = f2[t] + f2[NN+t] + f2[2*NN+t] + f2[3*NN+t];

    float myb = beta[t], myc = chi[t];
    float vBB  = myb * colB;                       // beta^T Delta beta
    float vGG  = myb * colG;                       // beta^T G beta  (= ||s||^2)
    float vBX  = myc * colB;                       // chi^T Delta beta
    float vXX  = myc * colX;                       // chi^T Dp chi
    float vLin = (t < Bc) ? d_RD[Bl[t]] : 0.f;     // beta^T RDelta
    float vQ   = (t < Bc) ? d_qd[Bl[t]] : 0.f;     // X1 . s

    float r0 = warpRed(vBB), r1 = warpRed(vGG), r2 = warpRed(vBX),
          r3 = warpRed(vXX), r4 = warpRed(vLin), r5 = warpRed(vQ);
    if (l == 0){ red[0][w]=r0; red[1][w]=r1; red[2][w]=r2;
                 red[3][w]=r3; red[4][w]=r4; red[5][w]=r5; }
    __syncthreads();
    if (t == 0){
        float BB=0.f, GG=0.f, BX=0.f, XX=0.f, LIN=0.f, QS=0.f;
#pragma unroll
        for (int i = 0; i < 10; i++){
            BB += red[0][i]; GG += red[1][i]; BX += red[2][i];
            XX += red[3][i]; LIN += red[4][i]; QS += red[5][i];
        }
        const float M = 51040.f;                    // 320*319/2
        float Sv  = d_scal[0] + LIN + BB - 2.f*BX - XX;
        float Z2  = d_scal[2] - 4.f*QS + 4.f*GG;    // ||X1 - 2 sum_B x||^2
        float Sv2 = 320.f * d_scal[1] - Z2;
        out[p] = (Sv2 - Sv*Sv/M) / (M - 1.f);
    }
}

extern "C" void kernel_launch(void* const* d_in, const int* in_sizes, int n_in,
                              void* d_out, int out_size){
    const float* data  = (const float*)d_in[0];
    const int*   ptype = (const int*)d_in[3];
    const int*   perms = (const int*)d_in[4];
    float* out = (float*)d_out;
    k_pre1<<<1, NN>>>(data);
    k_pre2<<<NN, NN>>>(data);
    k_pre3<<<1, NN>>>(data);
    k_main<<<1001, NN>>>(ptype, perms, out);
}

// round 4
// speedup vs baseline: 1.6718x; 1.6718x over previous
#include <cuda_runtime.h>
#include <cuda_fp16.h>

#define NN 320
#define DD 64

// Precomputed, perm-independent state (static device globals: no allocation).
__device__ __align__(16) __half2 d_DlG[NN*NN]; // (Delta, Gram) packed per element
__device__ __align__(16) __half  d_Dph[NN*NN]; // ||x_a - x_b||
__device__ float d_RD[NN];      // row sums of Delta (fp32)
__device__ float d_rowC[NN];    // per-row sum of Dp over b>a (fp32)
__device__ float d_sn[NN];      // squared norms
__device__ float d_qd[NN];      // X1 . x_a = row sum of Gram

__device__ __forceinline__ float warpRed(float v){
#pragma unroll
    for (int o = 16; o > 0; o >>= 1) v += __shfl_down_sync(0xffffffffu, v, o);
    return v;
}

// Fused precompute: one block per row a, thread = column b.
__global__ void __launch_bounds__(NN) k_pre(const float* __restrict__ x){
    __shared__ float xa[DD];
    __shared__ float sa_sh;
    __shared__ float red[3][10];
    int a = blockIdx.x, b = threadIdx.x;
    if (b < DD) xa[b] = x[a*DD + b];
    __syncthreads();
    const float4* xb = reinterpret_cast<const float4*>(x + b*DD);
    float g = 0.f, nb = 0.f;
#pragma unroll
    for (int i = 0; i < DD/4; i++){
        float4 v = xb[i];
        g  += xa[4*i]*v.x + xa[4*i+1]*v.y + xa[4*i+2]*v.z + xa[4*i+3]*v.w;
        nb += v.x*v.x + v.y*v.y + v.z*v.z + v.w*v.w;
    }
    if (b == a){ sa_sh = nb; d_sn[a] = nb; }
    __syncthreads();
    float sa = sa_sh;
    float dp = sqrtf(fmaxf(sa + nb - 2.f*g, 0.f));
    float dm = sqrtf(fmaxf(sa + nb + 2.f*g, 0.f));
    float dl = dm - dp;
    d_DlG[a*NN + b] = __floats2half2_rn(dl, g);
    d_Dph[a*NN + b] = __float2half_rn(dp);

    int w = b >> 5, l = b & 31;
    float v0 = warpRed(dl);
    float v1 = warpRed(b > a ? dp : 0.f);
    float v2 = warpRed(g);
    if (l == 0){ red[0][w] = v0; red[1][w] = v1; red[2][w] = v2; }
    __syncthreads();
    if (b == 0){
        float s0 = 0.f, s1 = 0.f, s2 = 0.f;
#pragma unroll
        for (int i = 0; i < 10; i++){ s0 += red[0][i]; s1 += red[1][i]; s2 += red[2][i]; }
        d_RD[a]   = s0;   // row sum of Delta
        d_rowC[a] = s1;   // row sum of Dp over b>a
        d_qd[a]   = s2;   // X1 . x_a
    }
}

// Main: one block per dataset (block 0 = identity, block p>=1 = perms[p-1]).
// 320 threads = 80 quad-columns x 4 row-slices. 128-bit half2 gathers.
__global__ void __launch_bounds__(NN, 4) k_main(const int* __restrict__ ptype,
                                                const int* __restrict__ perms,
                                                float* __restrict__ out){
    __shared__ float beta[NN], chi[NN];
    __shared__ int   Bl[NN], Cl[NN];
    __shared__ int   offB[10], offC[10], cnt[2];
    __shared__ float4 s4[3][4][NN/4];     // [Dl | G | Dp][slice][quad-col]
    __shared__ float red[9][10];

    int t = threadIdx.x, p = blockIdx.x;
    int w = t >> 5, l = t & 31;

    beta[t] = 0.f; chi[t] = 0.f;
    __syncthreads();

    int a  = (p == 0) ? t : perms[(p-1)*NN + t];
    int fn = (ptype[t] == 0);
    int fa = (ptype[a] == 0);
    int u  = (a != t) && fn && fa;          // this position's row is negated
    if (fn) chi[a]  = 1.f;                  // image of a fermion position
    if (u)  beta[a] = 1.f;                  // image of a negated position

    // Deterministic warp-ballot compaction into index lists
    unsigned ballB = __ballot_sync(0xffffffffu, u);
    unsigned ballC = __ballot_sync(0xffffffffu, fn);
    if (l == 0){ offB[w] = __popc(ballB); offC[w] = __popc(ballC); }
    __syncthreads();
    if (t == 0){
        int sB = 0, sC = 0;
#pragma unroll
        for (int i = 0; i < 10; i++){
            int bb = offB[i]; offB[i] = sB; sB += bb;
            int cc = offC[i]; offC[i] = sC; sC += cc;
        }
        cnt[0] = sB; cnt[1] = sC;
    }
    __syncthreads();
    unsigned lt = (1u << l) - 1u;
    if (u)  Bl[offB[w] + __popc(ballB & lt)] = a;
    if (fn) Cl[offC[w] + __popc(ballC & lt)] = a;
    __syncthreads();
    int Bc = cnt[0], Cc = cnt[1];

    // Column-sum gathers. slice s handles rows i ≡ s (mod 4), thread covers 4 cols.
    int s = t / 80;           // 0..3
    int q = t - s*80;         // 0..79 quad-column
    const __half2* pBG = d_DlG + 4*q;    // 4 half2 = 16B per row
    const __half*  pDp = d_Dph + 4*q;    // 4 half  =  8B per row

    float4 aB = make_float4(0.f,0.f,0.f,0.f);
    float4 aG = make_float4(0.f,0.f,0.f,0.f);
    float4 aX = make_float4(0.f,0.f,0.f,0.f);
#pragma unroll 2
    for (int i = s; i < Bc; i += 4){
        int r = Bl[i] * NN;
        uint4 uv = *reinterpret_cast<const uint4*>(pBG + r);
        float2 f0 = __half22float2(*reinterpret_cast<__half2*>(&uv.x));
        float2 f1 = __half22float2(*reinterpret_cast<__half2*>(&uv.y));
        float2 f2 = __half22float2(*reinterpret_cast<__half2*>(&uv.z));
        float2 f3 = __half22float2(*reinterpret_cast<__half2*>(&uv.w));
        aB.x += f0.x; aG.x += f0.y;
        aB.y += f1.x; aG.y += f1.y;
        aB.z += f2.x; aG.z += f2.y;
        aB.w += f3.x; aG.w += f3.y;
    }
#pragma unroll 4
    for (int i = s; i < Cc; i += 4){
        int r = Cl[i] * NN;
        uint2 uv = *reinterpret_cast<const uint2*>(pDp + r);
        float2 f0 = __half22float2(*reinterpret_cast<__half2*>(&uv.x));
        float2 f1 = __half22float2(*reinterpret_cast<__half2*>(&uv.y));
        aX.x += f0.x; aX.y += f0.y; aX.z += f1.x; aX.w += f1.y;
    }
    s4[0][s][q] = aB;
    s4[1][s][q] = aG;
    s4[2][s][q] = aX;
    __syncthreads();

    // Per-column totals (thread t = column t), then weighted reductions.
    const float* f0p = reinterpret_cast<const float*>(s4[0]);
    const float* f1p = reinterpret_cast<const float*>(s4[1]);
    const float* f2p = reinterpret_cast<const float*>(s4[2]);
    float colB = f0p[t] + f0p[NN+t] + f0p[2*NN+t] + f0p[3*NN+t];
    float colG = f1p[t] + f1p[NN+t] + f1p[2*NN+t] + f1p[3*NN+t];
    float colX = f2p[t] + f2p[NN+t] + f2p[2*NN+t] + f2p[3*NN+t];

    float myb = beta[t], myc = chi[t];
    float vBB  = myb * colB;                       // beta^T Delta beta
    float vGG  = myb * colG;                       // beta^T G beta
    float vBX  = myc * colB;                       // chi^T Delta beta
    float vXX  = myc * colX;                       // chi^T Dp chi
    float vLin = (t < Bc) ? d_RD[Bl[t]] : 0.f;     // beta^T RDelta
    float vQ   = (t < Bc) ? d_qd[Bl[t]] : 0.f;     // X1 . sum_B x

    float r0 = warpRed(vBB), r1 = warpRed(vGG), r2 = warpRed(vBX),
          r3 = warpRed(vXX), r4 = warpRed(vLin), r5 = warpRed(vQ),
          r6 = warpRed(d_rowC[t]),                 // -> C_Dp
          r7 = warpRed(d_sn[t]),                   // -> S1
          r8 = warpRed(d_qd[t]);                   // -> ||X1||^2
    if (l == 0){ red[0][w]=r0; red[1][w]=r1; red[2][w]=r2;
                 red[3][w]=r3; red[4][w]=r4; red[5][w]=r5;
                 red[6][w]=r6; red[7][w]=r7; red[8][w]=r8; }
    __syncthreads();
    if (t == 0){
        float BB=0.f, GG=0.f, BX=0.f, XX=0.f, LIN=0.f, QS=0.f,
              CDP=0.f, S1=0.f, X1SQ=0.f;
#pragma unroll
        for (int i = 0; i < 10; i++){
            BB += red[0][i]; GG += red[1][i]; BX += red[2][i];
            XX += red[3][i]; LIN += red[4][i]; QS += red[5][i];
            CDP += red[6][i]; S1 += red[7][i]; X1SQ += red[8][i];
        }
        const float M = 51040.f;                    // 320*319/2
        float Sv  = CDP + LIN + BB - 2.f*BX - XX;
        float Z2  = X1SQ - 4.f*QS + 4.f*GG;         // ||X1 - 2 sum_B x||^2
        float Sv2 = 320.f * S1 - Z2;
        out[p] = (Sv2 - Sv*Sv/M) / (M - 1.f);
    }
}

extern "C" void kernel_launch(void* const* d_in, const int* in_sizes, int n_in,
                              void* d_out, int out_size){
    const float* data  = (const float*)d_in[0];
    const int*   ptype = (const int*)d_in[3];
    const int*   perms = (const int*)d_in[4];
    float* out = (float*)d_out;
    k_pre <<<NN,   NN>>>(data);
    k_main<<<1001, NN>>>(ptype, perms, out);
}

// round 5
// speedup vs baseline: 1.6879x; 1.0096x over previous
#include <cuda_runtime.h>
#include <cuda_fp16.h>

#define NN 320
#define DD 64

// Precomputed, perm-independent state (static device globals: no allocation).
__device__ __align__(16) __half2 d_DlG[NN*NN]; // (Delta, Gram) packed per element
__device__ __align__(16) __half  d_Dph[NN*NN]; // ||x_a - x_b||
__device__ float d_RD[NN];      // row sums of Delta (fp32)
__device__ float d_rowC[NN];    // per-row sum of Dp over b>a (fp32)
__device__ float d_sn[NN];      // squared norms
__device__ float d_qd[NN];      // X1 . x_a = row sum of Gram

__device__ __forceinline__ float warpRed(float v){
#pragma unroll
    for (int o = 16; o > 0; o >>= 1) v += __shfl_down_sync(0xffffffffu, v, o);
    return v;
}

// Fused precompute: one block per row a, thread = column b.
__global__ void __launch_bounds__(NN) k_pre(const float* __restrict__ x){
    __shared__ float xa[DD];
    __shared__ float sa_sh;
    __shared__ float red[3][10];
    int a = blockIdx.x, b = threadIdx.x;
    if (b < DD) xa[b] = x[a*DD + b];
    __syncthreads();
    const float4* xb = reinterpret_cast<const float4*>(x + b*DD);
    float g = 0.f, nb = 0.f;
#pragma unroll
    for (int i = 0; i < DD/4; i++){
        float4 v = xb[i];
        g  += xa[4*i]*v.x + xa[4*i+1]*v.y + xa[4*i+2]*v.z + xa[4*i+3]*v.w;
        nb += v.x*v.x + v.y*v.y + v.z*v.z + v.w*v.w;
    }
    if (b == a){ sa_sh = nb; d_sn[a] = nb; }
    __syncthreads();
    float sa = sa_sh;
    float dp = sqrtf(fmaxf(sa + nb - 2.f*g, 0.f));
    float dm = sqrtf(fmaxf(sa + nb + 2.f*g, 0.f));
    float dl = dm - dp;
    d_DlG[a*NN + b] = __floats2half2_rn(dl, g);
    d_Dph[a*NN + b] = __float2half_rn(dp);

    int w = b >> 5, l = b & 31;
    float v0 = warpRed(dl);
    float v1 = warpRed(b > a ? dp : 0.f);
    float v2 = warpRed(g);
    if (l == 0){ red[0][w] = v0; red[1][w] = v1; red[2][w] = v2; }
    __syncthreads();
    if (b == 0){
        float s0 = 0.f, s1 = 0.f, s2 = 0.f;
#pragma unroll
        for (int i = 0; i < 10; i++){ s0 += red[0][i]; s1 += red[1][i]; s2 += red[2][i]; }
        d_RD[a]   = s0;   // row sum of Delta
        d_rowC[a] = s1;   // row sum of Dp over b>a
        d_qd[a]   = s2;   // X1 . x_a
    }
}

// Main: one block per dataset (block 0 = identity, block p>=1 = perms[p-1]).
// 320 threads = 80 quad-columns x 4 row-slices. HADD2 accumulation with
// chunked fp32 promotion every 32 gathered rows.
__global__ void __launch_bounds__(NN, 4) k_main(const int* __restrict__ ptype,
                                                const int* __restrict__ perms,
                                                float* __restrict__ out){
    __shared__ float beta[NN], chi[NN];
    __shared__ int   Bl[NN], Cl[NN];
    __shared__ int   offB[10], offC[10], cnt[2];
    __shared__ float4 s4[3][4][NN/4];     // [Dl | G | Dp][slice][quad-col]
    __shared__ float red[9][10];

    int t = threadIdx.x, p = blockIdx.x;
    int w = t >> 5, l = t & 31;

    beta[t] = 0.f; chi[t] = 0.f;
    __syncthreads();

    int a  = (p == 0) ? t : perms[(p-1)*NN + t];
    int fn = (ptype[t] == 0);
    int fa = (ptype[a] == 0);
    int u  = (a != t) && fn && fa;          // this position's row is negated
    if (fn) chi[a]  = 1.f;                  // image of a fermion position
    if (u)  beta[a] = 1.f;                  // image of a negated position

    // Deterministic warp-ballot compaction into index lists
    unsigned ballB = __ballot_sync(0xffffffffu, u);
    unsigned ballC = __ballot_sync(0xffffffffu, fn);
    if (l == 0){ offB[w] = __popc(ballB); offC[w] = __popc(ballC); }
    __syncthreads();
    if (t == 0){
        int sB = 0, sC = 0;
#pragma unroll
        for (int i = 0; i < 10; i++){
            int bb = offB[i]; offB[i] = sB; sB += bb;
            int cc = offC[i]; offC[i] = sC; sC += cc;
        }
        cnt[0] = sB; cnt[1] = sC;
    }
    __syncthreads();
    unsigned lt = (1u << l) - 1u;
    if (u)  Bl[offB[w] + __popc(ballB & lt)] = a;
    if (fn) Cl[offC[w] + __popc(ballC & lt)] = a;
    __syncthreads();
    int Bc = cnt[0], Cc = cnt[1];

    // Column-sum gathers. slice s handles rows i ≡ s (mod 4), thread covers 4 cols.
    int s = t / 80;           // 0..3
    int q = t - s*80;         // 0..79 quad-column
    const __half2* pBG = d_DlG + 4*q;    // 4 half2 = 16B per row
    const __half*  pDp = d_Dph + 4*q;    // 4 half  =  8B per row

    float4 aB = make_float4(0.f,0.f,0.f,0.f);
    float4 aG = make_float4(0.f,0.f,0.f,0.f);
    float4 aX = make_float4(0.f,0.f,0.f,0.f);
    const __half2 hz = __float2half2_rn(0.f);

    // B loop: (Delta,G) pairs; one HADD2 per column per row.
    for (int i0 = s; i0 < Bc; i0 += 32){
        int lim = min(i0 + 32, Bc);
        __half2 c0 = hz, c1 = hz, c2 = hz, c3 = hz;
#pragma unroll 8
        for (int i = i0; i < lim; i += 4){
            int r = Bl[i] * NN;
            uint4 uv = *reinterpret_cast<const uint4*>(pBG + r);
            c0 = __hadd2(c0, *reinterpret_cast<__half2*>(&uv.x));
            c1 = __hadd2(c1, *reinterpret_cast<__half2*>(&uv.y));
            c2 = __hadd2(c2, *reinterpret_cast<__half2*>(&uv.z));
            c3 = __hadd2(c3, *reinterpret_cast<__half2*>(&uv.w));
        }
        float2 f0 = __half22float2(c0), f1 = __half22float2(c1),
               f2 = __half22float2(c2), f3 = __half22float2(c3);
        aB.x += f0.x; aG.x += f0.y;
        aB.y += f1.x; aG.y += f1.y;
        aB.z += f2.x; aG.z += f2.y;
        aB.w += f3.x; aG.w += f3.y;
    }

    // C loop: Dp; half2 covers two adjacent columns.
    for (int i0 = s; i0 < Cc; i0 += 32){
        int lim = min(i0 + 32, Cc);
        __half2 d0 = hz, d1 = hz;
#pragma unroll 8
        for (int i = i0; i < lim; i += 4){
            int r = Cl[i] * NN;
            uint2 uv = *reinterpret_cast<const uint2*>(pDp + r);
            d0 = __hadd2(d0, *reinterpret_cast<__half2*>(&uv.x));
            d1 = __hadd2(d1, *reinterpret_cast<__half2*>(&uv.y));
        }
        float2 f0 = __half22float2(d0), f1 = __half22float2(d1);
        aX.x += f0.x; aX.y += f0.y; aX.z += f1.x; aX.w += f1.y;
    }

    s4[0][s][q] = aB;
    s4[1][s][q] = aG;
    s4[2][s][q] = aX;
    __syncthreads();

    // Per-column totals (thread t = column t), then weighted reductions.
    const float* f0p = reinterpret_cast<const float*>(s4[0]);
    const float* f1p = reinterpret_cast<const float*>(s4[1]);
    const float* f2p = reinterpret_cast<const float*>(s4[2]);
    float colB = f0p[t] + f0p[NN+t] + f0p[2*NN+t] + f0p[3*NN+t];
    float colG = f1p[t] + f1p[NN+t] + f1p[2*NN+t] + f1p[3*NN+t];
    float colX = f2p[t] + f2p[NN+t] + f2p[2*NN+t] + f2p[3*NN+t];

    float myb = beta[t], myc = chi[t];
    float vBB  = myb * colB;                       // beta^T Delta beta
    float vGG  = myb * colG;                       // beta^T G beta
    float vBX  = myc * colB;                       // chi^T Delta beta
    float vXX  = myc * colX;                       // chi^T Dp chi
    float vLin = (t < Bc) ? d_RD[Bl[t]] : 0.f;     // beta^T RDelta
    float vQ   = (t < Bc) ? d_qd[Bl[t]] : 0.f;     // X1 . sum_B x

    float r0 = warpRed(vBB), r1 = warpRed(vGG), r2 = warpRed(vBX),
          r3 = warpRed(vXX), r4 = warpRed(vLin), r5 = warpRed(vQ),
          r6 = warpRed(d_rowC[t]),                 // -> C_Dp
          r7 = warpRed(d_sn[t]),                   // -> S1
          r8 = warpRed(d_qd[t]);                   // -> ||X1||^2
    if (l == 0){ red[0][w]=r0; red[1][w]=r1; red[2][w]=r2;
                 red[3][w]=r3; red[4][w]=r4; red[5][w]=r5;
                 red[6][w]=r6; red[7][w]=r7; red[8][w]=r8; }
    __syncthreads();
    if (t == 0){
        float BB=0.f, GG=0.f, BX=0.f, XX=0.f, LIN=0.f, QS=0.f,
              CDP=0.f, S1=0.f, X1SQ=0.f;
#pragma unroll
        for (int i = 0; i < 10; i++){
            BB += red[0][i]; GG += red[1][i]; BX += red[2][i];
            XX += red[3][i]; LIN += red[4][i]; QS += red[5][i];
            CDP += red[6][i]; S1 += red[7][i]; X1SQ += red[8][i];
        }
        const float M = 51040.f;                    // 320*319/2
        float Sv  = CDP + LIN + BB - 2.f*BX - XX;
        float Z2  = X1SQ - 4.f*QS + 4.f*GG;         // ||X1 - 2 sum_B x||^2
        float Sv2 = 320.f * S1 - Z2;
        out[p] = (Sv2 - Sv*Sv/M) / (M - 1.f);
    }
}

extern "C" void kernel_launch(void* const* d_in, const int* in_sizes, int n_in,
                              void* d_out, int out_size){
    const float* data  = (const float*)d_in[0];
    const int*   ptype = (const int*)d_in[3];
    const int*   perms = (const int*)d_in[4];
    float* out = (float*)d_out;
    k_pre <<<NN,   NN>>>(data);
    k_main<<<1001, NN>>>(ptype, perms, out);
}